// round 2
// baseline (speedup 1.0000x reference)
#include <cuda_runtime.h>
#include <cstdint>

#define D      256
#define NSRC   4096
#define NTOT   8192
#define NBLK   64            // NTOT / 128
#define NPAIRS 2080          // NBLK*(NBLK+1)/2
#define BM     128
#define BK     32
#define EPSV   1e-6

// Scratch (no allocations allowed in kernel_launch)
__device__ float  g_sq[NTOT];
__device__ float  g_colpart[NBLK * D];
__device__ float  g_c;                 // 1 / (16*bandwidth + eps)
__device__ double g_partials[NPAIRS];

// ---------------------------------------------------------------------------
// Pass 1a: per-row squared norms. One warp per row.
// ---------------------------------------------------------------------------
__global__ void k_sq(const float* __restrict__ src, const float* __restrict__ tgt) {
    int warp = (blockIdx.x * blockDim.x + threadIdx.x) >> 5;
    int lane = threadIdx.x & 31;
    if (warp >= NTOT) return;
    const float* row = (warp < NSRC) ? (src + (size_t)warp * D)
                                     : (tgt + (size_t)(warp - NSRC) * D);
    float s = 0.f;
#pragma unroll
    for (int j = 0; j < D / 32; j++) {
        float v = row[lane + 32 * j];
        s += v * v;
    }
#pragma unroll
    for (int o = 16; o; o >>= 1) s += __shfl_xor_sync(0xffffffffu, s, o);
    if (lane == 0) g_sq[warp] = s;
}

// ---------------------------------------------------------------------------
// Pass 1b: column-sum partials. Block b owns rows [b*128, b*128+128).
// ---------------------------------------------------------------------------
__global__ void k_col(const float* __restrict__ src, const float* __restrict__ tgt) {
    int b = blockIdx.x;
    int d = threadIdx.x;
    const float* base = (b < NBLK / 2) ? (src + (size_t)b * 128 * D)
                                       : (tgt + (size_t)(b - NBLK / 2) * 128 * D);
    float s = 0.f;
#pragma unroll 8
    for (int i = 0; i < 128; i++) s += base[(size_t)i * D + d];
    g_colpart[b * D + d] = s;
}

// ---------------------------------------------------------------------------
// Pass 1c: bandwidth via closed form:
//   sum(L2) = 2*n*sum(sq) - 2*||colsum||^2
// Single block, fixed-order reductions -> deterministic.
// ---------------------------------------------------------------------------
__global__ void k_bw() {
    int d = threadIdx.x;
    double cs = 0.0;
#pragma unroll 8
    for (int b = 0; b < NBLK; b++) cs += (double)g_colpart[b * D + d];
    double ssq_term = cs * cs;
    double sq_sum = 0.0;
    for (int i = d; i < NTOT; i += 256) sq_sum += (double)g_sq[i];

    __shared__ double sh1[256], sh2[256];
    sh1[d] = ssq_term;
    sh2[d] = sq_sum;
    __syncthreads();
    for (int o = 128; o; o >>= 1) {
        if (d < o) { sh1[d] += sh1[d + o]; sh2[d] += sh2[d + o]; }
        __syncthreads();
    }
    if (d == 0) {
        double n     = (double)NTOT;
        double sumL2 = 2.0 * (n * sh2[0] - sh1[0]);
        double bw    = sumL2 / (n * n - n) / 4.0;   // / KERNEL_MUL^(KERNEL_NUM//2)
        g_c = (float)(1.0 / (bw * 16.0 + EPSV));
    }
}

// ---------------------------------------------------------------------------
// Pass 2: triangular tile sweep. CTA = one (bi<=bj) 128x128 tile.
// Classic 8x8 register-blocked SGEMM body, fused MMD epilogue:
//   L2 = sq_i + sq_j - 2*dot
//   u  = exp(-L2 * c);  K = u + u^2 + u^4 + u^8 + u^16
// Sign constant per tile; accumulate in double; no atomics.
// ---------------------------------------------------------------------------
__global__ void __launch_bounds__(256) k_main(const float* __restrict__ src,
                                              const float* __restrict__ tgt) {
    // decode linear blockIdx -> (bi, bj) with bi <= bj
    int bi = 0, rem = blockIdx.x;
    while (rem >= NBLK - bi) { rem -= NBLK - bi; bi++; }
    int bj = bi + rem;

    const float* A = (bi < NBLK / 2) ? (src + (size_t)bi * 128 * D)
                                     : (tgt + (size_t)(bi - NBLK / 2) * 128 * D);
    const float* B = (bj < NBLK / 2) ? (src + (size_t)bj * 128 * D)
                                     : (tgt + (size_t)(bj - NBLK / 2) * 128 * D);

    __shared__ float As[BK][BM + 4];
    __shared__ float Bs[BK][BM + 4];

    int t  = threadIdx.x;
    int tx = t & 15;        // 0..15 -> col group of 8
    int ty = t >> 4;        // 0..15 -> row group of 8

    float acc[8][8];
#pragma unroll
    for (int i = 0; i < 8; i++)
#pragma unroll
        for (int j = 0; j < 8; j++) acc[i][j] = 0.f;

    int lr = t >> 3;          // 0..31
    int lc = (t & 7) * 4;     // 0,4,...,28

    for (int k0 = 0; k0 < D; k0 += BK) {
#pragma unroll
        for (int p = 0; p < 4; p++) {
            int r = p * 32 + lr;
            float4 va = *(const float4*)(A + (size_t)r * D + k0 + lc);
            float4 vb = *(const float4*)(B + (size_t)r * D + k0 + lc);
            As[lc + 0][r] = va.x; As[lc + 1][r] = va.y;
            As[lc + 2][r] = va.z; As[lc + 3][r] = va.w;
            Bs[lc + 0][r] = vb.x; Bs[lc + 1][r] = vb.y;
            Bs[lc + 2][r] = vb.z; Bs[lc + 3][r] = vb.w;
        }
        __syncthreads();
#pragma unroll
        for (int kk = 0; kk < BK; kk++) {
            float a[8], b[8];
            *(float4*)(a)     = *(const float4*)&As[kk][ty * 8];
            *(float4*)(a + 4) = *(const float4*)&As[kk][ty * 8 + 4];
            *(float4*)(b)     = *(const float4*)&Bs[kk][tx * 8];
            *(float4*)(b + 4) = *(const float4*)&Bs[kk][tx * 8 + 4];
#pragma unroll
            for (int i = 0; i < 8; i++)
#pragma unroll
                for (int j = 0; j < 8; j++) acc[i][j] += a[i] * b[j];
        }
        __syncthreads();
    }

    // epilogue
    float c = g_c;
    float sqa[8], sqb[8];
#pragma unroll
    for (int i = 0; i < 8; i++) {
        sqa[i] = g_sq[bi * 128 + ty * 8 + i];
        sqb[i] = g_sq[bj * 128 + tx * 8 + i];
    }
    double tsum = 0.0;
#pragma unroll
    for (int i = 0; i < 8; i++) {
#pragma unroll
        for (int j = 0; j < 8; j++) {
            float L2 = sqa[i] + sqb[j] - 2.f * acc[i][j];
            float u  = __expf(-L2 * c);         // k=4 kernel; others are powers
            float u2 = u * u;
            float u4 = u2 * u2;
            float u8 = u4 * u4;
            float s  = u + u2 + u4 + u8 + u8 * u8;
            tsum += (double)s;
        }
    }

    __shared__ double red[256];
    red[t] = tsum;
    __syncthreads();
    for (int o = 128; o; o >>= 1) {
        if (t < o) red[t] += red[t + o];
        __syncthreads();
    }
    if (t == 0) {
        double w   = (bi == bj) ? 1.0 : 2.0;                      // symmetry weight
        double sgn = ((bi < NBLK / 2) == (bj < NBLK / 2)) ? 1.0 : -1.0;
        g_partials[blockIdx.x] = w * sgn * red[0];
    }
}

// ---------------------------------------------------------------------------
// Pass 3: deterministic final reduction -> scalar mean.
// ---------------------------------------------------------------------------
__global__ void k_final(float* __restrict__ out) {
    __shared__ double red[256];
    int t = threadIdx.x;
    double s = 0.0;
    for (int i = t; i < NPAIRS; i += 256) s += g_partials[i];
    red[t] = s;
    __syncthreads();
    for (int o = 128; o; o >>= 1) {
        if (t < o) red[t] += red[t + o];
        __syncthreads();
    }
    if (t == 0) out[0] = (float)(red[0] / ((double)NSRC * (double)NSRC));
}

// ---------------------------------------------------------------------------
extern "C" void kernel_launch(void* const* d_in, const int* in_sizes, int n_in,
                              void* d_out, int out_size) {
    const float* src = (const float*)d_in[0];
    const float* tgt = (const float*)d_in[1];
    (void)in_sizes; (void)n_in; (void)out_size;

    k_sq<<<NTOT / 8, 256>>>(src, tgt);      // 8 warps/block -> 8 rows/block
    k_col<<<NBLK, 256>>>(src, tgt);
    k_bw<<<1, 256>>>();
    k_main<<<NPAIRS, 256>>>(src, tgt);
    k_final<<<1, 256>>>((float*)d_out);
}